// round 15
// baseline (speedup 1.0000x reference)
#include <cuda_runtime.h>

// Net0: x[B,2] -> fc1(2,7)+ELU -> 19x fc(7,7)+ELU -> fc(7,2) -> log_softmax.
// R15: j-major single-asm-block layers at 64 regs -> 4 blocks/SM (8 warps/SMSP).
//   - state[j] dies after step j -> peak live ~64 regs (vs 80 for i-major)
//   - bias init via LDS directly into accumulator regs (no reg-reg movs)
//   - 14 independent FMA chains per layer (best ILP of any variant so far)
// Algebra (validated R9-R14): state t = z*log2e; G = log2e*(elu(z)+1)
//   = log2e*exp2(min(t,0)) + max(t,0); mid weights RAW; bias' = (b-rowsum)*log2e;
//   fc21: logits = (ln2*Wo)*G + (bo - rowsum(Wo)).

constexpr int H       = 7;
constexpr int NMID    = 19;
constexpr int THREADS = 256;

typedef unsigned long long u64;

__device__ __forceinline__ u64 pack2(float lo, float hi) {
    u64 r; asm("mov.b64 %0, {%1, %2};" : "=l"(r) : "f"(lo), "f"(hi)); return r;
}
__device__ __forceinline__ void unpack2(u64 v, float& lo, float& hi) {
    asm("mov.b64 {%0, %1}, %2;" : "=f"(lo), "=f"(hi) : "l"(v));
}
__device__ __forceinline__ u64 fma2(u64 a, u64 b, u64 c) {
    u64 d; asm("fma.rn.f32x2 %0, %1, %2, %3;" : "=l"(d) : "l"(a), "l"(b), "l"(c));
    return d;
}
__device__ __forceinline__ float ex2f(float x) {
    float r; asm("ex2.approx.f32 %0, %1;" : "=f"(r) : "f"(x)); return r;
}
__device__ __forceinline__ float eluG1(float t) {   // scalar, fc1 only
    return fmaf(1.44269504088896340736f, ex2f(fminf(t, 0.0f)), fmaxf(t, 0.0f));
}

// ---- PTX text macros ----
// G = log2e*exp2(min(t,0)) + max(t,0); unique regs per instance.
#define ELUS(ACC,G,E0,E1,M0,M1) \
  "mov.b64 {" E0 "," E1 "}, " ACC ";\n\t" \
  "min.f32 " M0 "," E0 ", 0f00000000;\n\t" \
  "min.f32 " M1 "," E1 ", 0f00000000;\n\t" \
  "ex2.approx.f32 " M0 "," M0 ";\n\t" \
  "ex2.approx.f32 " M1 "," M1 ";\n\t" \
  "max.f32 " E0 "," E0 ", 0f00000000;\n\t" \
  "max.f32 " E1 "," E1 ", 0f00000000;\n\t" \
  "fma.rn.f32 " E0 "," M0 ", 0f3FB8AA3B," E0 ";\n\t" \
  "fma.rn.f32 " E1 "," M1 ", 0f3FB8AA3B," E1 ";\n\t" \
  "mov.b64 " G ", {" E0 "," E1 "};\n\t"

// j-major step: all 14 accumulators take one multiply from state pair (SA,SB).
#define JSTEP(O0,O1,O2,O3,SA,SB) \
  "ld.shared.v2.b64 {w0,w1},[%14+" O0 "];\n\t" \
  "ld.shared.v2.b64 {w2,w3},[%14+" O1 "];\n\t" \
  "fma.rn.f32x2 cA0, w0," SA ", cA0;\n\t" \
  "fma.rn.f32x2 cB0, w0," SB ", cB0;\n\t" \
  "fma.rn.f32x2 cA1, w1," SA ", cA1;\n\t" \
  "fma.rn.f32x2 cB1, w1," SB ", cB1;\n\t" \
  "fma.rn.f32x2 cA2, w2," SA ", cA2;\n\t" \
  "fma.rn.f32x2 cB2, w2," SB ", cB2;\n\t" \
  "fma.rn.f32x2 cA3, w3," SA ", cA3;\n\t" \
  "fma.rn.f32x2 cB3, w3," SB ", cB3;\n\t" \
  "ld.shared.v2.b64 {w4,w5},[%14+" O2 "];\n\t" \
  "ld.shared.b64 w6,[%14+" O3 "];\n\t" \
  "fma.rn.f32x2 cA4, w4," SA ", cA4;\n\t" \
  "fma.rn.f32x2 cB4, w4," SB ", cB4;\n\t" \
  "fma.rn.f32x2 cA5, w5," SA ", cA5;\n\t" \
  "fma.rn.f32x2 cB5, w5," SB ", cB5;\n\t" \
  "fma.rn.f32x2 cA6, w6," SA ", cA6;\n\t" \
  "fma.rn.f32x2 cB6, w6," SB ", cB6;\n\t"

__global__ void __launch_bounds__(THREADS, 4)
net0_kernel(const float* __restrict__ x,
            const float* __restrict__ W1, const float* __restrict__ b1,
            const float* __restrict__ Wm, const float* __restrict__ bm,
            const float* __restrict__ Wo, const float* __restrict__ bo,
            float* __restrict__ out, int nQuads)
{
    __shared__ __align__(16) float2 sFc1[H * 4];        // {w0d,w1d,bd,pad} x log2e
    __shared__ __align__(16) float2 sMid[NMID * 64];    // j-major, raw W, bias' t-scale
    __shared__ __align__(16) float2 sFcO[2 * 8];        // (ln2*Wo)d + bias-fold d

    const float LOG2E = 1.44269504088896340736f;
    const float LN2   = 0.69314718055994530942f;

    for (int idx = threadIdx.x; idx < H * 4; idx += THREADS) {
        int i = idx >> 2, k = idx & 3;
        float v = (k < 2) ? W1[i * 2 + k] * LOG2E
                          : (k == 2 ? b1[i] * LOG2E : 0.0f);
        sFc1[idx] = make_float2(v, v);
    }
    // j-major per layer (512 B): jblk[j] at j*64: {W[0][j]d..W[6][j]d,pad};
    // bias block at 448: {b'0d..b'6d,pad} with b' = (b - rowsum(W))*log2e.
    for (int idx = threadIdx.x; idx < NMID * 64; idx += THREADS) {
        int l   = idx >> 6;
        int r   = idx & 63;
        int blk = r >> 3;             // 0..7
        int k   = r & 7;              // 0..7  (output neuron i)
        float v = 0.0f;
        if (blk < 7) {                // weight block j=blk, neuron i=k (RAW)
            if (k < 7) v = Wm[(l * H + k) * H + blk];
        } else {                      // bias block, t-scale
            if (k < 7) {
                float s = 0.0f;
                for (int j = 0; j < H; j++) s += Wm[(l * H + k) * H + j];
                v = (bm[l * H + k] - s) * LOG2E;
            }
        }
        sMid[idx] = make_float2(v, v);
    }
    for (int idx = threadIdx.x; idx < 16; idx += THREADS) {
        int r = idx >> 3, k = idx & 7;
        float v;
        if (k < 7) {
            v = Wo[r * H + k] * LN2;
        } else {
            float s = 0.0f;
            for (int j = 0; j < H; j++) s += Wo[r * H + j];
            v = bo[r] - s;
        }
        sFcO[idx] = make_float2(v, v);
    }
    __syncthreads();

    // Volatile producer of sbase AFTER the barrier: pins all dependent
    // layer blocks after __syncthreads.
    unsigned sbase;
    {
        unsigned long long gen = (unsigned long long)__cvta_generic_to_shared(sMid);
        asm volatile("cvt.u32.u64 %0, %1;" : "=r"(sbase) : "l"(gen));
    }

    int q = blockIdx.x * THREADS + threadIdx.x;   // 4 rows per thread
    if (q >= nQuads) return;

    float4 xa = reinterpret_cast<const float4*>(x)[2 * q + 0];
    float4 xb = reinterpret_cast<const float4*>(x)[2 * q + 1];

    // ---- fc1 (t-scale) + ELU(G), scalar ----
    float g[4][H];
#pragma unroll
    for (int i = 0; i < H; i++) {
        float w0 = sFc1[i * 4 + 0].x;
        float w1 = sFc1[i * 4 + 1].x;
        float bb = sFc1[i * 4 + 2].x;
        g[0][i] = eluG1(fmaf(w0, xa.x, fmaf(w1, xa.y, bb)));
        g[1][i] = eluG1(fmaf(w0, xa.z, fmaf(w1, xa.w, bb)));
        g[2][i] = eluG1(fmaf(w0, xb.x, fmaf(w1, xb.y, bb)));
        g[3][i] = eluG1(fmaf(w0, xb.z, fmaf(w1, xb.w, bb)));
    }
    u64 h0a = pack2(g[0][0], g[1][0]), h0b = pack2(g[2][0], g[3][0]);
    u64 h1a = pack2(g[0][1], g[1][1]), h1b = pack2(g[2][1], g[3][1]);
    u64 h2a = pack2(g[0][2], g[1][2]), h2b = pack2(g[2][2], g[3][2]);
    u64 h3a = pack2(g[0][3], g[1][3]), h3b = pack2(g[2][3], g[3][3]);
    u64 h4a = pack2(g[0][4], g[1][4]), h4b = pack2(g[2][4], g[3][4]);
    u64 h5a = pack2(g[0][5], g[1][5]), h5b = pack2(g[2][5], g[3][5]);
    u64 h6a = pack2(g[0][6], g[1][6]), h6b = pack2(g[2][6], g[3][6]);

    // ---- fc2..fc20: 19 j-major single-asm layers ----
    // Bias loads init the accumulators (twice via LDS: A and B copies).
    // state[j] is consumed exactly once (step j) then dies; ELUs at the end
    // write the (dead) state regs. No WAR hazards.
#pragma unroll 1
    for (int l = 0; l < NMID; l++) {
        unsigned saddr = sbase + (unsigned)l * 512u;
        asm(
            "{\n\t"
            ".reg .b64 w<8>, cA<7>, cB<7>;\n\t"
            ".reg .f32 e<28>, m<28>;\n\t"
            "ld.shared.v2.b64 {cA0,cA1},[%14+448];\n\t"
            "ld.shared.v2.b64 {cA2,cA3},[%14+464];\n\t"
            "ld.shared.v2.b64 {cA4,cA5},[%14+480];\n\t"
            "ld.shared.b64 cA6,[%14+496];\n\t"
            "ld.shared.v2.b64 {cB0,cB1},[%14+448];\n\t"
            "ld.shared.v2.b64 {cB2,cB3},[%14+464];\n\t"
            "ld.shared.v2.b64 {cB4,cB5},[%14+480];\n\t"
            "ld.shared.b64 cB6,[%14+496];\n\t"
            JSTEP(  "0", "16", "32", "48", "%0", "%7")
            JSTEP( "64", "80", "96","112", "%1", "%8")
            JSTEP("128","144","160","176", "%2", "%9")
            JSTEP("192","208","224","240", "%3","%10")
            JSTEP("256","272","288","304", "%4","%11")
            JSTEP("320","336","352","368", "%5","%12")
            JSTEP("384","400","416","432", "%6","%13")
            ELUS("cA0", "%0","e0","e1","m0","m1")
            ELUS("cB0", "%7","e2","e3","m2","m3")
            ELUS("cA1", "%1","e4","e5","m4","m5")
            ELUS("cB1", "%8","e6","e7","m6","m7")
            ELUS("cA2", "%2","e8","e9","m8","m9")
            ELUS("cB2", "%9","e10","e11","m10","m11")
            ELUS("cA3", "%3","e12","e13","m12","m13")
            ELUS("cB3","%10","e14","e15","m14","m15")
            ELUS("cA4", "%4","e16","e17","m16","m17")
            ELUS("cB4","%11","e18","e19","m18","m19")
            ELUS("cA5", "%5","e20","e21","m20","m21")
            ELUS("cB5","%12","e22","e23","m22","m23")
            ELUS("cA6", "%6","e24","e25","m24","m25")
            ELUS("cB6","%13","e26","e27","m26","m27")
            "}"
            : "+l"(h0a), "+l"(h1a), "+l"(h2a), "+l"(h3a),
              "+l"(h4a), "+l"(h5a), "+l"(h6a),
              "+l"(h0b), "+l"(h1b), "+l"(h2b), "+l"(h3b),
              "+l"(h4b), "+l"(h5b), "+l"(h6b)
            : "r"(saddr));
    }

    // ---- fc21: logits = (ln2*Wo)*G + bias-fold ----
    u64 lpa[2], lpb[2];
#pragma unroll
    for (int r = 0; r < 2; r++) {
        const ulonglong2* p = reinterpret_cast<const ulonglong2*>(&sFcO[r * 8]);
        ulonglong2 q0 = p[0], q1 = p[1], q2 = p[2], q3 = p[3];
        u64 acca = q3.y, accb = q3.y;
        acca = fma2(q0.x, h0a, acca);  accb = fma2(q0.x, h0b, accb);
        acca = fma2(q0.y, h1a, acca);  accb = fma2(q0.y, h1b, accb);
        acca = fma2(q1.x, h2a, acca);  accb = fma2(q1.x, h2b, accb);
        acca = fma2(q1.y, h3a, acca);  accb = fma2(q1.y, h3b, accb);
        acca = fma2(q2.x, h4a, acca);  accb = fma2(q2.x, h4b, accb);
        acca = fma2(q2.y, h5a, acca);  accb = fma2(q2.y, h5b, accb);
        acca = fma2(q3.x, h6a, acca);  accb = fma2(q3.x, h6b, accb);
        lpa[r] = acca;  lpb[r] = accb;
    }

    float a0lo, a0hi, a1lo, a1hi, b0lo, b0hi, b1lo, b1hi;
    unpack2(lpa[0], a0lo, a0hi);  unpack2(lpa[1], a1lo, a1hi);
    unpack2(lpb[0], b0lo, b0hi);  unpack2(lpb[1], b1lo, b1hi);

    auto lsm = [](float l0, float l1, float& o0, float& o1) {
        float m   = fmaxf(l0, l1);
        float s   = ex2f((l0 - m) * 1.44269504088896340736f)
                  + ex2f((l1 - m) * 1.44269504088896340736f);
        float lse = m + __logf(s);
        o0 = l0 - lse;  o1 = l1 - lse;
    };

    float4 oa, ob;
    lsm(a0lo, a1lo, oa.x, oa.y);
    lsm(a0hi, a1hi, oa.z, oa.w);
    lsm(b0lo, b1lo, ob.x, ob.y);
    lsm(b0hi, b1hi, ob.z, ob.w);

    reinterpret_cast<float4*>(out)[2 * q + 0] = oa;
    reinterpret_cast<float4*>(out)[2 * q + 1] = ob;
}

extern "C" void kernel_launch(void* const* d_in, const int* in_sizes, int n_in,
                              void* d_out, int out_size)
{
    const float* x  = (const float*)d_in[0];
    const float* W1 = (const float*)d_in[1];
    const float* b1 = (const float*)d_in[2];
    const float* Wm = (const float*)d_in[3];
    const float* bm = (const float*)d_in[4];
    const float* Wo = (const float*)d_in[5];
    const float* bo = (const float*)d_in[6];
    float* out = (float*)d_out;

    int nQuads = in_sizes[0] / 8;   // x is [B,2]; 4 rows per thread
    int grid = (nQuads + THREADS - 1) / THREADS;
    net0_kernel<<<grid, THREADS>>>(x, W1, b1, Wm, bm, Wo, bo, out, nQuads);
}